// round 11
// baseline (speedup 1.0000x reference)
#include <cuda_runtime.h>
#include <stdint.h>

// z[e, :] = h[src[e], :] * h[dst[e], :]
// h: [N=50000, D=64] fp32 (12.8 MB, L2-resident), src/dst int32,
// out: [E=800000, 64] fp32.
//
// Final form. Evidence from R4-R10: kernel is bound by the DRAM write-drain
// of the output stream (~165 MB/replay at ~4.1 TB/s ~= 40 us); MLP shaping,
// occupancy, L1 bypass, SMEM+TMA staging, and L2 residency pinning were all
// neutral or worse. So: leanest possible instruction stream --
// 8 threads/edge, sequential edge mapping (best wall time), one 256-bit
// gather per source row, one 256-bit streaming store. Every warp access is
// full 128B lines.

static constexpr int D = 64;

__device__ __forceinline__ void ld_h8(const float* p, float* v) {
    uint32_t r0, r1, r2, r3, r4, r5, r6, r7;
    asm volatile(
        "ld.global.nc.v8.b32 {%0,%1,%2,%3,%4,%5,%6,%7}, [%8];"
        : "=r"(r0), "=r"(r1), "=r"(r2), "=r"(r3),
          "=r"(r4), "=r"(r5), "=r"(r6), "=r"(r7)
        : "l"(p));
    v[0] = __uint_as_float(r0); v[1] = __uint_as_float(r1);
    v[2] = __uint_as_float(r2); v[3] = __uint_as_float(r3);
    v[4] = __uint_as_float(r4); v[5] = __uint_as_float(r5);
    v[6] = __uint_as_float(r6); v[7] = __uint_as_float(r7);
}

__device__ __forceinline__ void st8_stream(float* p, const float* v) {
    asm volatile(
        "st.global.cs.v8.b32 [%0], {%1,%2,%3,%4,%5,%6,%7,%8};"
        :: "l"(p),
           "r"(__float_as_uint(v[0])), "r"(__float_as_uint(v[1])),
           "r"(__float_as_uint(v[2])), "r"(__float_as_uint(v[3])),
           "r"(__float_as_uint(v[4])), "r"(__float_as_uint(v[5])),
           "r"(__float_as_uint(v[6])), "r"(__float_as_uint(v[7]))
        : "memory");
}

__global__ void __launch_bounds__(256, 8) u_mul_v_kernel(
    const float* __restrict__ h,
    const int* __restrict__ src,
    const int* __restrict__ dst,
    float* __restrict__ out,
    int n_edges)
{
    const int t = blockIdx.x * 256 + threadIdx.x;
    const int e = t >> 3;                // sequential edge id
    const int j = (t & 7) * 8;           // float offset of this 32B chunk
    if (e >= n_edges) return;

    // 8 adjacent threads share each index -> L1 broadcast.
    const int s = __ldg(&src[e]);
    const int d = __ldg(&dst[e]);

    float a[8], b[8];
    ld_h8(h + (size_t)s * D + j, a);
    ld_h8(h + (size_t)d * D + j, b);

    float r[8];
#pragma unroll
    for (int i = 0; i < 8; i++) r[i] = a[i] * b[i];

    st8_stream(out + (size_t)e * D + j, r);
}

extern "C" void kernel_launch(void* const* d_in, const int* in_sizes, int n_in,
                              void* d_out, int out_size) {
    const float* h = (const float*)d_in[0];
    const int* src = (const int*)d_in[1];
    const int* dst = (const int*)d_in[2];
    float* out = (float*)d_out;

    const int n_edges = in_sizes[1];  // E = 800000
    const long long total = (long long)n_edges * 8;
    const int threads = 256;
    const int blocks = (int)((total + threads - 1) / threads);

    u_mul_v_kernel<<<blocks, threads>>>(h, src, dst, out, n_edges);
}

// round 12
// speedup vs baseline: 1.0988x; 1.0988x over previous
#include <cuda_runtime.h>
#include <stdint.h>

// z[e, :] = h[src[e], :] * h[dst[e], :]
// h: [N=50000, D=64] fp32 (12.8 MB, L2-resident), src/dst int32,
// out: [E=800000, 64] fp32.
//
// Operating point mapped over R4-R11:
//  - bound by output DRAM write drain (~165 MB/replay @ ~4.2 TB/s => ~40us);
//  - need ~4 outstanding gathers/thread at full occupancy (2 -> starved,
//    16 -> occupancy cliff);
//  - 256-bit accesses halve L1tex wavefronts (verified);
//  - sequential edge mapping gave the best wall time (store/index locality).
// R12 = 8 threads/edge x 2 adjacent edges/thread, LDG.256 gathers,
// st.global.cs.256 stores.

static constexpr int D = 64;

__device__ __forceinline__ void ld_h8(const float* p, float* v) {
    uint32_t r0, r1, r2, r3, r4, r5, r6, r7;
    asm volatile(
        "ld.global.nc.v8.b32 {%0,%1,%2,%3,%4,%5,%6,%7}, [%8];"
        : "=r"(r0), "=r"(r1), "=r"(r2), "=r"(r3),
          "=r"(r4), "=r"(r5), "=r"(r6), "=r"(r7)
        : "l"(p));
    v[0] = __uint_as_float(r0); v[1] = __uint_as_float(r1);
    v[2] = __uint_as_float(r2); v[3] = __uint_as_float(r3);
    v[4] = __uint_as_float(r4); v[5] = __uint_as_float(r5);
    v[6] = __uint_as_float(r6); v[7] = __uint_as_float(r7);
}

__device__ __forceinline__ void st8_stream(float* p, const float* v) {
    asm volatile(
        "st.global.cs.v8.b32 [%0], {%1,%2,%3,%4,%5,%6,%7,%8};"
        :: "l"(p),
           "r"(__float_as_uint(v[0])), "r"(__float_as_uint(v[1])),
           "r"(__float_as_uint(v[2])), "r"(__float_as_uint(v[3])),
           "r"(__float_as_uint(v[4])), "r"(__float_as_uint(v[5])),
           "r"(__float_as_uint(v[6])), "r"(__float_as_uint(v[7]))
        : "memory");
}

__global__ void __launch_bounds__(256, 8) u_mul_v_kernel(
    const float* __restrict__ h,
    const int* __restrict__ src,
    const int* __restrict__ dst,
    float* __restrict__ out,
    int n_edges)
{
    const int t = blockIdx.x * 256 + threadIdx.x;
    const int p = t >> 3;                // edge-pair id
    const int j = (t & 7) * 8;           // float offset of this 32B chunk

    const int e0 = 2 * p;                // adjacent edges
    const int e1 = 2 * p + 1;
    if (e0 >= n_edges) return;
    const bool has_e1 = (e1 < n_edges);

    // 8 adjacent threads share each index -> L1 broadcast; consecutive pairs
    // hit the same index cache lines.
    const int s0 = __ldg(&src[e0]);
    const int d0 = __ldg(&dst[e0]);
    const int s1 = has_e1 ? __ldg(&src[e1]) : 0;
    const int d1 = has_e1 ? __ldg(&dst[e1]) : 0;

    // Front-batch 4 outstanding 256-bit gathers (measured sweet spot).
    float a0[8], b0[8], a1[8], b1[8];
    ld_h8(h + (size_t)s0 * D + j, a0);
    ld_h8(h + (size_t)d0 * D + j, b0);
    ld_h8(h + (size_t)s1 * D + j, a1);
    ld_h8(h + (size_t)d1 * D + j, b1);

    float r0[8];
#pragma unroll
    for (int i = 0; i < 8; i++) r0[i] = a0[i] * b0[i];
    st8_stream(out + (size_t)e0 * D + j, r0);

    if (has_e1) {
        float r1[8];
#pragma unroll
        for (int i = 0; i < 8; i++) r1[i] = a1[i] * b1[i];
        st8_stream(out + (size_t)e1 * D + j, r1);
    }
}

extern "C" void kernel_launch(void* const* d_in, const int* in_sizes, int n_in,
                              void* d_out, int out_size) {
    const float* h = (const float*)d_in[0];
    const int* src = (const int*)d_in[1];
    const int* dst = (const int*)d_in[2];
    float* out = (float*)d_out;

    const int n_edges = in_sizes[1];              // E = 800000
    const int pairs = (n_edges + 1) / 2;          // 400000
    const long long total = (long long)pairs * 8;
    const int threads = 256;
    const int blocks = (int)((total + threads - 1) / threads);

    u_mul_v_kernel<<<blocks, threads>>>(h, src, dst, out, n_edges);
}

// round 13
// speedup vs baseline: 1.1030x; 1.0039x over previous
#include <cuda_runtime.h>
#include <stdint.h>

// z[e, :] = h[src[e], :] * h[dst[e], :]
// h: [N=50000, D=64] fp32 (12.8 MB, L2-resident), src/dst int32,
// out: [E=800000, 64] fp32.
//
// R13 A/B: identical to R12 (best kernel time, 39.5us) except output stores
// use DEFAULT policy instead of .cs. Mechanism: .cs force-drains output to
// DRAM; default write-back lets dirty output lines persist in L2 across
// back-to-back graph replays (re-dirtied in place, never drained). Risk:
// output flood evicts h -> gather DRAM misses; h is ~32x hotter per line
// than output, so LRU should protect it. This is the last untested lever.

static constexpr int D = 64;

__device__ __forceinline__ void ld_h8(const float* p, float* v) {
    uint32_t r0, r1, r2, r3, r4, r5, r6, r7;
    asm volatile(
        "ld.global.nc.v8.b32 {%0,%1,%2,%3,%4,%5,%6,%7}, [%8];"
        : "=r"(r0), "=r"(r1), "=r"(r2), "=r"(r3),
          "=r"(r4), "=r"(r5), "=r"(r6), "=r"(r7)
        : "l"(p));
    v[0] = __uint_as_float(r0); v[1] = __uint_as_float(r1);
    v[2] = __uint_as_float(r2); v[3] = __uint_as_float(r3);
    v[4] = __uint_as_float(r4); v[5] = __uint_as_float(r5);
    v[6] = __uint_as_float(r6); v[7] = __uint_as_float(r7);
}

__device__ __forceinline__ void st8_default(float* p, const float* v) {
    asm volatile(
        "st.global.v8.b32 [%0], {%1,%2,%3,%4,%5,%6,%7,%8};"
        :: "l"(p),
           "r"(__float_as_uint(v[0])), "r"(__float_as_uint(v[1])),
           "r"(__float_as_uint(v[2])), "r"(__float_as_uint(v[3])),
           "r"(__float_as_uint(v[4])), "r"(__float_as_uint(v[5])),
           "r"(__float_as_uint(v[6])), "r"(__float_as_uint(v[7]))
        : "memory");
}

__global__ void __launch_bounds__(256, 8) u_mul_v_kernel(
    const float* __restrict__ h,
    const int* __restrict__ src,
    const int* __restrict__ dst,
    float* __restrict__ out,
    int n_edges)
{
    const int t = blockIdx.x * 256 + threadIdx.x;
    const int p = t >> 3;                // edge-pair id
    const int j = (t & 7) * 8;           // float offset of this 32B chunk

    const int e0 = 2 * p;                // adjacent edges
    const int e1 = 2 * p + 1;
    if (e0 >= n_edges) return;
    const bool has_e1 = (e1 < n_edges);

    // 8 adjacent threads share each index -> L1 broadcast.
    const int s0 = __ldg(&src[e0]);
    const int d0 = __ldg(&dst[e0]);
    const int s1 = has_e1 ? __ldg(&src[e1]) : 0;
    const int d1 = has_e1 ? __ldg(&dst[e1]) : 0;

    // Front-batch 4 outstanding 256-bit gathers (measured sweet spot).
    float a0[8], b0[8], a1[8], b1[8];
    ld_h8(h + (size_t)s0 * D + j, a0);
    ld_h8(h + (size_t)d0 * D + j, b0);
    ld_h8(h + (size_t)s1 * D + j, a1);
    ld_h8(h + (size_t)d1 * D + j, b1);

    float r0[8];
#pragma unroll
    for (int i = 0; i < 8; i++) r0[i] = a0[i] * b0[i];
    st8_default(out + (size_t)e0 * D + j, r0);

    if (has_e1) {
        float r1[8];
#pragma unroll
        for (int i = 0; i < 8; i++) r1[i] = a1[i] * b1[i];
        st8_default(out + (size_t)e1 * D + j, r1);
    }
}

extern "C" void kernel_launch(void* const* d_in, const int* in_sizes, int n_in,
                              void* d_out, int out_size) {
    const float* h = (const float*)d_in[0];
    const int* src = (const int*)d_in[1];
    const int* dst = (const int*)d_in[2];
    float* out = (float*)d_out;

    const int n_edges = in_sizes[1];              // E = 800000
    const int pairs = (n_edges + 1) / 2;          // 400000
    const long long total = (long long)pairs * 8;
    const int threads = 256;
    const int blocks = (int)((total + threads - 1) / threads);

    u_mul_v_kernel<<<blocks, threads>>>(h, src, dst, out, n_edges);
}

// round 14
// speedup vs baseline: 1.1484x; 1.0411x over previous
#include <cuda_runtime.h>
#include <stdint.h>

// z[e, :] = h[src[e], :] * h[dst[e], :]
// h: [N=50000, D=64] fp32 (12.8 MB, L2-resident), src/dst: [E=800000] int32,
// out: [E, 64] fp32.
//
// FINAL (= R4, best measured wall time 39.2us; reproduced 39.4 by R5 twin).
// Session findings (R4-R13): kernel is at the memory-system floor
// (~165 MB/replay DRAM write drain @ ~4.2 TB/s + random 256B-row gathers
// served from L2). Falsified levers: more per-thread MLP, L1 bypass,
// SMEM+TMA store staging, L2 evict_last pinning, store policy, 256-bit
// accesses (faster under ncu's cold-cache regime, ~2us slower in the timed
// graph-replay steady state).
// Config: 8 threads/edge x 2 float4 per thread, sequential edge mapping,
// __stcs streaming stores. Every warp access is full 128B lines.

static constexpr int D = 64;
static constexpr int VEC_PER_ROW = D / 4;   // 16 float4 per row
static constexpr int THREADS_PER_EDGE = 8;  // 2 float4 per thread

__global__ void __launch_bounds__(256, 8) u_mul_v_kernel(
    const float4* __restrict__ h,        // [N, 16] as float4
    const int* __restrict__ src,         // [E] int32
    const int* __restrict__ dst,         // [E] int32
    float4* __restrict__ out,            // [E, 16] as float4
    int n_edges)
{
    const int t = blockIdx.x * 256 + threadIdx.x;
    const int e = t >> 3;                // edge id
    const int j = t & 7;                 // float4 pair id within row
    if (e >= n_edges) return;

    // 8 adjacent threads read the same index -> single line, L1 broadcast.
    const int s = __ldg(&src[e]);
    const int d = __ldg(&dst[e]);

    const float4* __restrict__ hs = h + (size_t)s * VEC_PER_ROW;
    const float4* __restrict__ hd = h + (size_t)d * VEC_PER_ROW;

    // Two independent load pairs -> 4 outstanding LDG.128 per thread.
    const float4 a0 = __ldg(hs + j);
    const float4 b0 = __ldg(hd + j);
    const float4 a1 = __ldg(hs + j + 8);
    const float4 b1 = __ldg(hd + j + 8);

    float4 r0, r1;
    r0.x = a0.x * b0.x; r0.y = a0.y * b0.y;
    r0.z = a0.z * b0.z; r0.w = a0.w * b0.w;
    r1.x = a1.x * b1.x; r1.y = a1.y * b1.y;
    r1.z = a1.z * b1.z; r1.w = a1.w * b1.w;

    float4* o = out + (size_t)e * VEC_PER_ROW + j;
    __stcs(o, r0);          // streaming: don't let output evict h from L2
    __stcs(o + 8, r1);
}

extern "C" void kernel_launch(void* const* d_in, const int* in_sizes, int n_in,
                              void* d_out, int out_size) {
    const float4* h = (const float4*)d_in[0];
    const int* src = (const int*)d_in[1];
    const int* dst = (const int*)d_in[2];
    float4* out = (float4*)d_out;

    const int n_edges = in_sizes[1];  // E = 800000
    const long long total = (long long)n_edges * THREADS_PER_EDGE;
    const int threads = 256;
    const int blocks = (int)((total + threads - 1) / threads);

    u_mul_v_kernel<<<blocks, threads>>>(h, src, dst, out, n_edges);
}